// round 14
// baseline (speedup 1.0000x reference)
#include <cuda_runtime.h>
#include <cuda_bf16.h>
#include <cstdint>

// Problem constants
#define NBATCH   16384
#define NAG      32
#define NOBS     64
#define NH       64
#define NACT     16
#define NROUNDS  2

#define NUNITS_U (NBATCH / 2)  // work unit = TWO batches (64 rows) per warp
#define NTHREADS 320           // 10 warps -> reg cap 204 (no-spill headroom)
#define NCTAS    152           // persistent: 1 CTA per SM

// SMEM weight strides (bf16 elements); conflict-free LDSM
#define W_STRIDE  72
#define W2_STRIDE 24

// ---------------------------------------------------------------------------
// Globals: bf16 weights (prologue-converted/decomposed) + persistent work counter
//   comm decomposition: [h|msg] @ Wc == h @ W1' + cs @ W2'
//   W1' = Wc_top - Wc_bot/31,  W2' = Wc_bot/31,  cs = per-batch column sum of h
// ---------------------------------------------------------------------------
__device__ __nv_bfloat16 g_enc_w  [NOBS * NH];
__device__ __nv_bfloat16 g_comm_w1[NROUNDS * NH * NH];
__device__ __nv_bfloat16 g_comm_w2[NROUNDS * NH * NH];
__device__ __nv_bfloat16 g_out_w1 [NH * NH];
__device__ __nv_bfloat16 g_out_w2 [NH * NACT];
__device__ unsigned      g_tile_ctr;

__global__ void convert_weights_kernel(const float* __restrict__ enc_w,
                                       const float* __restrict__ comm_w,
                                       const float* __restrict__ out_w1,
                                       const float* __restrict__ out_w2) {
    int i = blockIdx.x * blockDim.x + threadIdx.x;
    if (i == 0) g_tile_ctr = 0;
    if (i < NOBS * NH) g_enc_w[i]  = __float2bfloat16(enc_w[i]);
    if (i < NH * NH)   g_out_w1[i] = __float2bfloat16(out_w1[i]);
    if (i < NH * NACT) g_out_w2[i] = __float2bfloat16(out_w2[i]);
    if (i < NROUNDS * NH * NH) {
        int r = i / (NH * NH);
        int k = (i / NH) & (NH - 1);
        int j = i & (NH - 1);
        float top = comm_w[r * 2 * NH * NH + k * NH + j];
        float bot = comm_w[r * 2 * NH * NH + (NH + k) * NH + j];
        g_comm_w1[i] = __float2bfloat16(top - bot * (1.0f / 31.0f));
        g_comm_w2[i] = __float2bfloat16(bot * (1.0f / 31.0f));
    }
}

// ---------------------------------------------------------------------------
// PTX helpers
// ---------------------------------------------------------------------------
__device__ __forceinline__ uint32_t smem_u32(const void* p) {
    return (uint32_t)__cvta_generic_to_shared(p);
}
__device__ __forceinline__ void cp16(void* dst, const void* src) {
    asm volatile("cp.async.cg.shared.global [%0], [%1], 16;"
                 :: "r"(smem_u32(dst)), "l"(src));
}
__device__ __forceinline__ void cp_commit() { asm volatile("cp.async.commit_group;"); }
__device__ __forceinline__ void cp_wait_all() { asm volatile("cp.async.wait_group 0;"); }
__device__ __forceinline__ void l2pf(const void* p) {
    asm volatile("prefetch.global.L2 [%0];" :: "l"(p));
}

__device__ __forceinline__ void ldsm_x4_t(uint32_t& r0, uint32_t& r1, uint32_t& r2, uint32_t& r3, uint32_t a) {
    asm volatile("ldmatrix.sync.aligned.m8n8.x4.trans.shared.b16 {%0,%1,%2,%3}, [%4];"
                 : "=r"(r0), "=r"(r1), "=r"(r2), "=r"(r3) : "r"(a));
}
__device__ __forceinline__ void mma16816(float* c,
                                         uint32_t a0, uint32_t a1, uint32_t a2, uint32_t a3,
                                         uint32_t b0, uint32_t b1) {
    asm volatile("mma.sync.aligned.m16n8k16.row.col.f32.bf16.bf16.f32 "
                 "{%0,%1,%2,%3}, {%4,%5,%6,%7}, {%8,%9}, {%0,%1,%2,%3};"
                 : "+f"(c[0]), "+f"(c[1]), "+f"(c[2]), "+f"(c[3])
                 : "r"(a0), "r"(a1), "r"(a2), "r"(a3), "r"(b0), "r"(b1));
}

__device__ __forceinline__ uint32_t packbf(float x, float y) {
    __nv_bfloat162 p = __floats2bfloat162_rn(x, y);
    return *(uint32_t*)&p;
}
__device__ __forceinline__ uint32_t bf2add(uint32_t a, uint32_t b) {
    __nv_bfloat162 r = __hadd2(*(__nv_bfloat162*)&a, *(__nv_bfloat162*)&b);
    return *(uint32_t*)&r;
}

// One K=16 step, single A fragment, NT n-tiles (8 cols each)
template <int NT>
__device__ __forceinline__ void gemm_ktile(const uint32_t a[4],
                                           const __nv_bfloat16* sWk, int wstride,
                                           float acc[][4], int lane) {
#pragma unroll
    for (int nt = 0; nt < NT; nt += 2) {
        uint32_t b0, b1, b2, b3;
        ldsm_x4_t(b0, b1, b2, b3,
                  smem_u32(sWk + (lane & 15) * wstride + nt * 8 + ((lane >> 4) << 3)));
        mma16816(acc[nt], a[0], a[1], a[2], a[3], b0, b1);
        if (nt + 1 < NT) mma16816(acc[nt + 1], a[0], a[1], a[2], a[3], b2, b3);
    }
}

// One K=16 step for FOUR stripes (2 batches x 2 stripes): one LDSM pair -> 8 MMAs.
template <int NT>
__device__ __forceinline__ void gemm4_ktile(const uint32_t a0[4], const uint32_t a1[4],
                                            const uint32_t a2[4], const uint32_t a3[4],
                                            const __nv_bfloat16* sWk, int wstride,
                                            float acc0[][4], float acc1[][4],
                                            float acc2[][4], float acc3[][4], int lane) {
#pragma unroll
    for (int nt = 0; nt < NT; nt += 2) {
        uint32_t b0, b1, b2, b3;
        ldsm_x4_t(b0, b1, b2, b3,
                  smem_u32(sWk + (lane & 15) * wstride + nt * 8 + ((lane >> 4) << 3)));
        mma16816(acc0[nt], a0[0], a0[1], a0[2], a0[3], b0, b1);
        mma16816(acc1[nt], a1[0], a1[1], a1[2], a1[3], b0, b1);
        mma16816(acc2[nt], a2[0], a2[1], a2[2], a2[3], b0, b1);
        mma16816(acc3[nt], a3[0], a3[1], a3[2], a3[3], b0, b1);
        if (nt + 1 < NT) {
            mma16816(acc0[nt + 1], a0[0], a0[1], a0[2], a0[3], b2, b3);
            mma16816(acc1[nt + 1], a1[0], a1[1], a1[2], a1[3], b2, b3);
            mma16816(acc2[nt + 1], a2[0], a2[1], a2[2], a2[3], b2, b3);
            mma16816(acc3[nt + 1], a3[0], a3[1], a3[2], a3[3], b2, b3);
        }
    }
}

// bias + relu + pack a 32-col half (acc[4][4]) into 2 A-frag k-tiles (bf16x2 ops).
__device__ __forceinline__ void pack_h4(const float acc[][4], uint32_t hf[][4],
                                        const uint32_t* sBH, int c) {
    const __nv_bfloat162 z = __float2bfloat162_rn(0.0f);
#pragma unroll
    for (int tt = 0; tt < 2; ++tt) {
        uint32_t bA = sBH[8 * tt + c];
        uint32_t bB = sBH[8 * tt + 4 + c];
#pragma unroll
        for (int j = 0; j < 2; ++j) {
            uint32_t pa = packbf(acc[2*tt][2*j],   acc[2*tt][2*j + 1]);
            uint32_t pb = packbf(acc[2*tt+1][2*j], acc[2*tt+1][2*j + 1]);
            __nv_bfloat162 ra = __hmax2(__hadd2(*(__nv_bfloat162*)&pa, *(__nv_bfloat162*)&bA), z);
            __nv_bfloat162 rb = __hmax2(__hadd2(*(__nv_bfloat162*)&pb, *(__nv_bfloat162*)&bB), z);
            hf[tt][j]     = *(uint32_t*)&ra;
            hf[tt][2 + j] = *(uint32_t*)&rb;
        }
    }
}

// Coalesced obs A-fragment loader (float4 + shfl redistribute)
__device__ __forceinline__ void enc_frags(const float* __restrict__ obs,
                                          size_t rbase_row, int t,
                                          int lane, int gr, int c, uint32_t a[4]) {
    const float* p0 = obs + (rbase_row + gr) * NOBS + 16 * t + 4 * c;
    float4 F0 = __ldg((const float4*)p0);
    float4 F1 = __ldg((const float4*)(p0 + 8 * NOBS));
    uint32_t p0xy = packbf(F0.x, F0.y), p0zw = packbf(F0.z, F0.w);
    uint32_t p1xy = packbf(F1.x, F1.y), p1zw = packbf(F1.z, F1.w);
    int srcA = (lane & ~3) | (c >> 1);
    int srcB = srcA + 2;
    uint32_t txy, tzw;
    txy = __shfl_sync(0xffffffffu, p0xy, srcA);
    tzw = __shfl_sync(0xffffffffu, p0zw, srcA);
    a[0] = (c & 1) ? tzw : txy;
    txy = __shfl_sync(0xffffffffu, p1xy, srcA);
    tzw = __shfl_sync(0xffffffffu, p1zw, srcA);
    a[1] = (c & 1) ? tzw : txy;
    txy = __shfl_sync(0xffffffffu, p0xy, srcB);
    tzw = __shfl_sync(0xffffffffu, p0zw, srcB);
    a[2] = (c & 1) ? tzw : txy;
    txy = __shfl_sync(0xffffffffu, p1xy, srcB);
    tzw = __shfl_sync(0xffffffffu, p1zw, srcB);
    a[3] = (c & 1) ? tzw : txy;
}

// In-place dense relu layer over 2 batches x 2 stripes, N split into two halves.
// One LDSM pair feeds 8 MMAs. Half-0 output parks in a 32-reg temp; half-1 pack
// overwrites h (legal: all half-1 MMAs completed), then temp is copied in.
__device__ __forceinline__ void dense64_4(uint32_t (&h)[2][2][4][4],
                                          const __nv_bfloat16* W, const uint32_t* sBH,
                                          int lane, int c) {
    uint32_t th[2][2][2][4];   // half-0 packed output
#pragma unroll
    for (int nh = 0; nh < 2; ++nh) {
        float acc[4][4][4];
#pragma unroll
        for (int s = 0; s < 4; ++s)
#pragma unroll
            for (int nt = 0; nt < 4; ++nt) {
                acc[s][nt][0]=0.f; acc[s][nt][1]=0.f; acc[s][nt][2]=0.f; acc[s][nt][3]=0.f;
            }
#pragma unroll
        for (int t = 0; t < 4; ++t)
            gemm4_ktile<4>(h[0][0][t], h[0][1][t], h[1][0][t], h[1][1][t],
                           W + 16 * t * W_STRIDE + 32 * nh, W_STRIDE,
                           acc[0], acc[1], acc[2], acc[3], lane);
        if (nh == 0) {
            pack_h4(acc[0], th[0][0], sBH, c);
            pack_h4(acc[1], th[0][1], sBH, c);
            pack_h4(acc[2], th[1][0], sBH, c);
            pack_h4(acc[3], th[1][1], sBH, c);
        } else {
            pack_h4(acc[0], &h[0][0][2], sBH + 16, c);
            pack_h4(acc[1], &h[0][1][2], sBH + 16, c);
            pack_h4(acc[2], &h[1][0][2], sBH + 16, c);
            pack_h4(acc[3], &h[1][1][2], sBH + 16, c);
        }
    }
#pragma unroll
    for (int b = 0; b < 2; ++b)
#pragma unroll
        for (int st = 0; st < 2; ++st)
#pragma unroll
            for (int tt = 0; tt < 2; ++tt)
#pragma unroll
                for (int j = 0; j < 4; ++j)
                    h[b][st][tt][j] = th[b][st][tt][j];
}

// Comm round for 2 batches, rank-1 M-packed across batches (rows 0-7 = cs_b0,
// rows 8-15 = cs_b1 -> one R gemm serves both batches). In-place on h.
__device__ __forceinline__ void comm_round2(uint32_t (&h)[2][2][4][4],
                                            const __nv_bfloat16* Wc1, const __nv_bfloat16* Wc2,
                                            const uint32_t* sBH, int lane, int c) {
    // per-batch packed column sums (bf16x2 HADD2 + butterfly)
    uint32_t csPA[2][4], csPB[2][4];
#pragma unroll
    for (int b = 0; b < 2; ++b)
#pragma unroll
        for (int t = 0; t < 4; ++t) {
            uint32_t pA = bf2add(bf2add(h[b][0][t][0], h[b][0][t][1]),
                                 bf2add(h[b][1][t][0], h[b][1][t][1]));
            uint32_t pB = bf2add(bf2add(h[b][0][t][2], h[b][0][t][3]),
                                 bf2add(h[b][1][t][2], h[b][1][t][3]));
#pragma unroll
            for (int m = 4; m < 32; m <<= 1) {
                pA = bf2add(pA, __shfl_xor_sync(0xffffffffu, pA, m));
                pB = bf2add(pB, __shfl_xor_sync(0xffffffffu, pB, m));
            }
            csPA[b][t] = pA;
            csPB[b][t] = pB;
        }

    uint32_t th[2][2][2][4];
#pragma unroll
    for (int nh = 0; nh < 2; ++nh) {
        // R packed: A rows 0-7 = cs_b0, rows 8-15 = cs_b1
        float racc[4][4];
#pragma unroll
        for (int nt = 0; nt < 4; ++nt) {
            racc[nt][0]=0.f; racc[nt][1]=0.f; racc[nt][2]=0.f; racc[nt][3]=0.f;
        }
#pragma unroll
        for (int t = 0; t < 4; ++t) {
            uint32_t a[4];
            a[0] = csPA[0][t]; a[1] = csPA[1][t];
            a[2] = csPB[0][t]; a[3] = csPB[1][t];
            gemm_ktile<4>(a, Wc2 + 16 * t * W_STRIDE + 32 * nh, W_STRIDE, racc, lane);
        }
        // init acc from R: batch b gets racc[nt][2b..2b+1] replicated over rows
        float acc[4][4][4];
#pragma unroll
        for (int nt = 0; nt < 4; ++nt) {
            float l0 = racc[nt][0], h0 = racc[nt][1];
            float l1 = racc[nt][2], h1 = racc[nt][3];
#pragma unroll
            for (int st = 0; st < 2; ++st) {
                acc[st][nt][0] = l0; acc[st][nt][1] = h0;
                acc[st][nt][2] = l0; acc[st][nt][3] = h0;
                acc[2 + st][nt][0] = l1; acc[2 + st][nt][1] = h1;
                acc[2 + st][nt][2] = l1; acc[2 + st][nt][3] = h1;
            }
        }
#pragma unroll
        for (int t = 0; t < 4; ++t)
            gemm4_ktile<4>(h[0][0][t], h[0][1][t], h[1][0][t], h[1][1][t],
                           Wc1 + 16 * t * W_STRIDE + 32 * nh, W_STRIDE,
                           acc[0], acc[1], acc[2], acc[3], lane);
        if (nh == 0) {
            pack_h4(acc[0], th[0][0], sBH, c);
            pack_h4(acc[1], th[0][1], sBH, c);
            pack_h4(acc[2], th[1][0], sBH, c);
            pack_h4(acc[3], th[1][1], sBH, c);
        } else {
            pack_h4(acc[0], &h[0][0][2], sBH + 16, c);
            pack_h4(acc[1], &h[0][1][2], sBH + 16, c);
            pack_h4(acc[2], &h[1][0][2], sBH + 16, c);
            pack_h4(acc[3], &h[1][1][2], sBH + 16, c);
        }
    }
#pragma unroll
    for (int b = 0; b < 2; ++b)
#pragma unroll
        for (int st = 0; st < 2; ++st)
#pragma unroll
            for (int tt = 0; tt < 2; ++tt)
#pragma unroll
                for (int j = 0; j < 4; ++j)
                    h[b][st][tt][j] = th[b][st][tt][j];
}

// ---------------------------------------------------------------------------
// Persistent warp-autonomous CommNet kernel: 10 warps, 2 batches/warp,
// 4-stripe LDSM sharing (1 ldmatrix -> 8 MMAs), N-split, in-place layers.
// ---------------------------------------------------------------------------
__global__ void __launch_bounds__(NTHREADS, 1)
commnet_kernel(const float* __restrict__ obs,
               const float* __restrict__ enc_b,
               const float* __restrict__ comm_b,
               const float* __restrict__ out_b1,
               const float* __restrict__ out_b2,
               const int*   __restrict__ avail,
               float*       __restrict__ out) {
    extern __shared__ __align__(16) char smem_raw[];
    __nv_bfloat16* sWe  = (__nv_bfloat16*)smem_raw;                  // 64  x 72
    __nv_bfloat16* sWc1 = sWe  + NH * W_STRIDE;                      // 128 x 72 (2 rounds)
    __nv_bfloat16* sWc2 = sWc1 + NROUNDS * NH * W_STRIDE;            // 128 x 72 (2 rounds)
    __nv_bfloat16* sWo1 = sWc2 + NROUNDS * NH * W_STRIDE;            // 64  x 72
    __nv_bfloat16* sWo2 = sWo1 + NH * W_STRIDE;                      // 64  x 24
    uint32_t*      sBH  = (uint32_t*)(sWo2 + NH * W2_STRIDE);        // 128 bf16x2 pairs
    float*         sB2  = (float*)(sBH + 128);                       // 16 fp32 (out_b2)

    const int tid  = threadIdx.x;
    const int lane = tid & 31;
    const int c    = lane & 3;
    const int gr   = lane >> 2;

    // ---- prologue: stage weights via cp.async, biases packed to bf16x2 ----
    for (int i = tid; i < 512; i += NTHREADS) {
        int r = i >> 3, ci = i & 7;
        cp16(sWe + r * W_STRIDE + ci * 8, g_enc_w + r * NH + ci * 8);
    }
    for (int i = tid; i < 1024; i += NTHREADS) {
        int r = i >> 3, ci = i & 7;
        cp16(sWc1 + r * W_STRIDE + ci * 8, g_comm_w1 + r * NH + ci * 8);
    }
    for (int i = tid; i < 1024; i += NTHREADS) {
        int r = i >> 3, ci = i & 7;
        cp16(sWc2 + r * W_STRIDE + ci * 8, g_comm_w2 + r * NH + ci * 8);
    }
    for (int i = tid; i < 512; i += NTHREADS) {
        int r = i >> 3, ci = i & 7;
        cp16(sWo1 + r * W_STRIDE + ci * 8, g_out_w1 + r * NH + ci * 8);
    }
    for (int i = tid; i < 128; i += NTHREADS) {
        int r = i >> 1, ci = i & 1;
        cp16(sWo2 + r * W2_STRIDE + ci * 8, g_out_w2 + r * NACT + ci * 8);
    }
    cp_commit();
    // bias pairs: enc [0..32), comm rd0 [32..64), comm rd1 [64..96), out1 [96..128)
    if (tid < 32) sBH[tid]      = packbf(enc_b[2*tid],  enc_b[2*tid+1]);
    if (tid < 64) sBH[32 + tid] = packbf(comm_b[2*tid], comm_b[2*tid+1]);
    if (tid < 32) sBH[96 + tid] = packbf(out_b1[2*tid], out_b1[2*tid+1]);
    if (tid < 16) sB2[tid]      = out_b2[tid];
    cp_wait_all();
    __syncthreads();

    // ---- per-warp unit loop (unit = 2 batches = 64 rows) ----
    unsigned u;
    if (lane == 0) u = atomicAdd(&g_tile_ctr, 1u);
    u = __shfl_sync(0xffffffffu, u, 0);

    uint32_t h[2][2][4][4];              // [batch][stripe][ktile][frag]

    while (u < NUNITS_U) {
        const size_t urow0 = (size_t)u * 64;

        // ---- encoder: h = relu(obs @ enc_w + enc_b), 4-stripe shared LDSM ----
        {
            uint32_t ofrag[2][2][4][4];
#pragma unroll
            for (int b = 0; b < 2; ++b)
#pragma unroll
                for (int st = 0; st < 2; ++st)
#pragma unroll
                    for (int t = 0; t < 4; ++t)
                        enc_frags(obs, urow0 + 32 * b + 16 * st, t, lane, gr, c,
                                  ofrag[b][st][t]);
#pragma unroll
            for (int nh = 0; nh < 2; ++nh) {
                float acc[4][4][4];
#pragma unroll
                for (int s = 0; s < 4; ++s)
#pragma unroll
                    for (int nt = 0; nt < 4; ++nt) {
                        acc[s][nt][0]=0.f; acc[s][nt][1]=0.f; acc[s][nt][2]=0.f; acc[s][nt][3]=0.f;
                    }
#pragma unroll
                for (int t = 0; t < 4; ++t)
                    gemm4_ktile<4>(ofrag[0][0][t], ofrag[0][1][t],
                                   ofrag[1][0][t], ofrag[1][1][t],
                                   sWe + 16 * t * W_STRIDE + 32 * nh, W_STRIDE,
                                   acc[0], acc[1], acc[2], acc[3], lane);
                pack_h4(acc[0], &h[0][0][2 * nh], sBH + 16 * nh, c);
                pack_h4(acc[1], &h[0][1][2 * nh], sBH + 16 * nh, c);
                pack_h4(acc[2], &h[1][0][2 * nh], sBH + 16 * nh, c);
                pack_h4(acc[3], &h[1][1][2 * nh], sBH + 16 * nh, c);
            }
        }

        // ---- grab next unit, prefetch its obs+avail to L2 ----
        unsigned un;
        if (lane == 0) un = atomicAdd(&g_tile_ctr, 1u);
        un = __shfl_sync(0xffffffffu, un, 0);
        if (un < NUNITS_U) {
            const char* ob = (const char*)(obs + (size_t)un * 64 * NOBS);
#pragma unroll
            for (int i = 0; i < 4; ++i) l2pf(ob + lane * 128 + i * 4096);
            l2pf((const char*)(avail + (size_t)un * 64 * NACT) + lane * 128);
        }

        // ---- comm rounds (in-place, rank-1 M-packed across both batches) ----
        comm_round2(h, sWc1,                 sWc2,                 sBH + 32, lane, c);
        comm_round2(h, sWc1 + NH * W_STRIDE, sWc2 + NH * W_STRIDE, sBH + 64, lane, c);

        // ---- out1 (in-place) ----
        dense64_4(h, sWo1, sBH + 96, lane, c);

        // ---- hoist avail loads (overlap L2 latency with out2 MMAs) ----
        int2 av[4][2][2];
        {
            int colb = 2 * c;
#pragma unroll
            for (int s2 = 0; s2 < 4; ++s2)
#pragma unroll
                for (int nt = 0; nt < 2; ++nt)
#pragma unroll
                    for (int half = 0; half < 2; ++half) {
                        size_t grow = urow0 + (size_t)(s2 >> 1) * 32 + (s2 & 1) * 16
                                      + gr + 8 * half;
                        av[s2][nt][half] = __ldg((const int2*)(avail + grow * NACT + nt * 8 + colb));
                    }
        }

        // ---- out2 shared across all 4 stripes (1 ldmatrix -> 8 MMAs) ----
        float acc2[4][2][4];
#pragma unroll
        for (int s2 = 0; s2 < 4; ++s2)
#pragma unroll
            for (int nt = 0; nt < 2; ++nt) {
                acc2[s2][nt][0]=0.f; acc2[s2][nt][1]=0.f; acc2[s2][nt][2]=0.f; acc2[s2][nt][3]=0.f;
            }
#pragma unroll
        for (int t = 0; t < 4; ++t) {
            uint32_t b0, b1, b2, b3;
            ldsm_x4_t(b0, b1, b2, b3,
                      smem_u32(sWo2 + (16 * t + (lane & 15)) * W2_STRIDE + ((lane >> 4) << 3)));
#pragma unroll
            for (int s2 = 0; s2 < 4; ++s2) {
                const uint32_t* A = h[s2 >> 1][s2 & 1][t];
                mma16816(acc2[s2][0], A[0], A[1], A[2], A[3], b0, b1);
                mma16816(acc2[s2][1], A[0], A[1], A[2], A[3], b2, b3);
            }
        }

        // ---- epilogue: bias + mask + store ----
        {
            int colb = 2 * c;
#pragma unroll
            for (int s2 = 0; s2 < 4; ++s2) {
                size_t rowb = urow0 + (size_t)(s2 >> 1) * 32 + (s2 & 1) * 16;
#pragma unroll
                for (int nt = 0; nt < 2; ++nt) {
                    int col  = nt * 8 + colb;
                    float b0 = sB2[col], b1 = sB2[col + 1];
#pragma unroll
                    for (int half = 0; half < 2; ++half) {
                        size_t grow = rowb + gr + 8 * half;
                        int2 a = av[s2][nt][half];
                        float q0 = acc2[s2][nt][half * 2 + 0] + b0;
                        float q1 = acc2[s2][nt][half * 2 + 1] + b1;
                        if (a.x == 0) q0 = -1e10f;
                        if (a.y == 0) q1 = -1e10f;
                        *(float2*)(out + grow * NACT + col) = make_float2(q0, q1);
                    }
                }
            }
        }

        u = un;
    }
}

#define SMEM_BYTES ((64*72 + 2*64*72 + 2*64*72 + 64*72 + 64*24) * 2 + 128 * 4 + 16 * 4 + 64)

// ---------------------------------------------------------------------------
extern "C" void kernel_launch(void* const* d_in, const int* in_sizes, int n_in,
                              void* d_out, int out_size) {
    const float* obs    = (const float*)d_in[0];
    const float* enc_w  = (const float*)d_in[1];
    const float* enc_b  = (const float*)d_in[2];
    const float* comm_w = (const float*)d_in[3];
    const float* comm_b = (const float*)d_in[4];
    const float* out_w1 = (const float*)d_in[5];
    const float* out_b1 = (const float*)d_in[6];
    const float* out_w2 = (const float*)d_in[7];
    const float* out_b2 = (const float*)d_in[8];
    const int*   avail  = (const int*)d_in[9];
    float* out = (float*)d_out;

    cudaFuncSetAttribute(commnet_kernel, cudaFuncAttributeMaxDynamicSharedMemorySize, SMEM_BYTES);

    convert_weights_kernel<<<64, 256>>>(enc_w, comm_w, out_w1, out_w2);
    commnet_kernel<<<NCTAS, NTHREADS, SMEM_BYTES>>>(
        obs, enc_b, comm_b, out_b1, out_b2, avail, out);
}

// round 15
// speedup vs baseline: 1.0287x; 1.0287x over previous
#include <cuda_runtime.h>
#include <cuda_bf16.h>
#include <cstdint>

// Problem constants
#define NBATCH   16384
#define NAG      32
#define NOBS     64
#define NH       64
#define NACT     16
#define NROUNDS  2

#define NUNITS_U (NBATCH / 2)  // work unit = TWO batches (64 rows) per warp
#define NTHREADS 384           // 12 warps -> 3/SMSP (reg cap 170; R14 needs 168)
#define NCTAS    152           // persistent: 1 CTA per SM

// SMEM weight strides (bf16 elements); conflict-free LDSM
#define W_STRIDE  72
#define W2_STRIDE 24

// ---------------------------------------------------------------------------
// Globals: bf16 weights (prologue-converted/decomposed) + persistent work counter
//   comm decomposition: [h|msg] @ Wc == h @ W1' + cs @ W2'
//   W1' = Wc_top - Wc_bot/31,  W2' = Wc_bot/31,  cs = per-batch column sum of h
// ---------------------------------------------------------------------------
__device__ __nv_bfloat16 g_enc_w  [NOBS * NH];
__device__ __nv_bfloat16 g_comm_w1[NROUNDS * NH * NH];
__device__ __nv_bfloat16 g_comm_w2[NROUNDS * NH * NH];
__device__ __nv_bfloat16 g_out_w1 [NH * NH];
__device__ __nv_bfloat16 g_out_w2 [NH * NACT];
__device__ unsigned      g_tile_ctr;

__global__ void convert_weights_kernel(const float* __restrict__ enc_w,
                                       const float* __restrict__ comm_w,
                                       const float* __restrict__ out_w1,
                                       const float* __restrict__ out_w2) {
    int i = blockIdx.x * blockDim.x + threadIdx.x;
    if (i == 0) g_tile_ctr = 0;
    if (i < NOBS * NH) g_enc_w[i]  = __float2bfloat16(enc_w[i]);
    if (i < NH * NH)   g_out_w1[i] = __float2bfloat16(out_w1[i]);
    if (i < NH * NACT) g_out_w2[i] = __float2bfloat16(out_w2[i]);
    if (i < NROUNDS * NH * NH) {
        int r = i / (NH * NH);
        int k = (i / NH) & (NH - 1);
        int j = i & (NH - 1);
        float top = comm_w[r * 2 * NH * NH + k * NH + j];
        float bot = comm_w[r * 2 * NH * NH + (NH + k) * NH + j];
        g_comm_w1[i] = __float2bfloat16(top - bot * (1.0f / 31.0f));
        g_comm_w2[i] = __float2bfloat16(bot * (1.0f / 31.0f));
    }
}

// ---------------------------------------------------------------------------
// PTX helpers
// ---------------------------------------------------------------------------
__device__ __forceinline__ uint32_t smem_u32(const void* p) {
    return (uint32_t)__cvta_generic_to_shared(p);
}
__device__ __forceinline__ void cp16(void* dst, const void* src) {
    asm volatile("cp.async.cg.shared.global [%0], [%1], 16;"
                 :: "r"(smem_u32(dst)), "l"(src));
}
__device__ __forceinline__ void cp_commit() { asm volatile("cp.async.commit_group;"); }
__device__ __forceinline__ void cp_wait_all() { asm volatile("cp.async.wait_group 0;"); }
__device__ __forceinline__ void l2pf(const void* p) {
    asm volatile("prefetch.global.L2 [%0];" :: "l"(p));
}

__device__ __forceinline__ void ldsm_x4_t(uint32_t& r0, uint32_t& r1, uint32_t& r2, uint32_t& r3, uint32_t a) {
    asm volatile("ldmatrix.sync.aligned.m8n8.x4.trans.shared.b16 {%0,%1,%2,%3}, [%4];"
                 : "=r"(r0), "=r"(r1), "=r"(r2), "=r"(r3) : "r"(a));
}
__device__ __forceinline__ void mma16816(float* c,
                                         uint32_t a0, uint32_t a1, uint32_t a2, uint32_t a3,
                                         uint32_t b0, uint32_t b1) {
    asm volatile("mma.sync.aligned.m16n8k16.row.col.f32.bf16.bf16.f32 "
                 "{%0,%1,%2,%3}, {%4,%5,%6,%7}, {%8,%9}, {%0,%1,%2,%3};"
                 : "+f"(c[0]), "+f"(c[1]), "+f"(c[2]), "+f"(c[3])
                 : "r"(a0), "r"(a1), "r"(a2), "r"(a3), "r"(b0), "r"(b1));
}

__device__ __forceinline__ uint32_t packbf(float x, float y) {
    __nv_bfloat162 p = __floats2bfloat162_rn(x, y);
    return *(uint32_t*)&p;
}
__device__ __forceinline__ uint32_t bf2add(uint32_t a, uint32_t b) {
    __nv_bfloat162 r = __hadd2(*(__nv_bfloat162*)&a, *(__nv_bfloat162*)&b);
    return *(uint32_t*)&r;
}

// One K=16 step, single A fragment, NT n-tiles (8 cols each)
template <int NT>
__device__ __forceinline__ void gemm_ktile(const uint32_t a[4],
                                           const __nv_bfloat16* sWk, int wstride,
                                           float acc[][4], int lane) {
#pragma unroll
    for (int nt = 0; nt < NT; nt += 2) {
        uint32_t b0, b1, b2, b3;
        ldsm_x4_t(b0, b1, b2, b3,
                  smem_u32(sWk + (lane & 15) * wstride + nt * 8 + ((lane >> 4) << 3)));
        mma16816(acc[nt], a[0], a[1], a[2], a[3], b0, b1);
        if (nt + 1 < NT) mma16816(acc[nt + 1], a[0], a[1], a[2], a[3], b2, b3);
    }
}

// One K=16 step for FOUR stripes (2 batches x 2 stripes): one LDSM pair -> 8 MMAs.
template <int NT>
__device__ __forceinline__ void gemm4_ktile(const uint32_t a0[4], const uint32_t a1[4],
                                            const uint32_t a2[4], const uint32_t a3[4],
                                            const __nv_bfloat16* sWk, int wstride,
                                            float acc0[][4], float acc1[][4],
                                            float acc2[][4], float acc3[][4], int lane) {
#pragma unroll
    for (int nt = 0; nt < NT; nt += 2) {
        uint32_t b0, b1, b2, b3;
        ldsm_x4_t(b0, b1, b2, b3,
                  smem_u32(sWk + (lane & 15) * wstride + nt * 8 + ((lane >> 4) << 3)));
        mma16816(acc0[nt], a0[0], a0[1], a0[2], a0[3], b0, b1);
        mma16816(acc1[nt], a1[0], a1[1], a1[2], a1[3], b0, b1);
        mma16816(acc2[nt], a2[0], a2[1], a2[2], a2[3], b0, b1);
        mma16816(acc3[nt], a3[0], a3[1], a3[2], a3[3], b0, b1);
        if (nt + 1 < NT) {
            mma16816(acc0[nt + 1], a0[0], a0[1], a0[2], a0[3], b2, b3);
            mma16816(acc1[nt + 1], a1[0], a1[1], a1[2], a1[3], b2, b3);
            mma16816(acc2[nt + 1], a2[0], a2[1], a2[2], a2[3], b2, b3);
            mma16816(acc3[nt + 1], a3[0], a3[1], a3[2], a3[3], b2, b3);
        }
    }
}

// bias + relu + pack a 32-col half (acc[4][4]) into 2 A-frag k-tiles (bf16x2 ops).
__device__ __forceinline__ void pack_h4(const float acc[][4], uint32_t hf[][4],
                                        const uint32_t* sBH, int c) {
    const __nv_bfloat162 z = __float2bfloat162_rn(0.0f);
#pragma unroll
    for (int tt = 0; tt < 2; ++tt) {
        uint32_t bA = sBH[8 * tt + c];
        uint32_t bB = sBH[8 * tt + 4 + c];
#pragma unroll
        for (int j = 0; j < 2; ++j) {
            uint32_t pa = packbf(acc[2*tt][2*j],   acc[2*tt][2*j + 1]);
            uint32_t pb = packbf(acc[2*tt+1][2*j], acc[2*tt+1][2*j + 1]);
            __nv_bfloat162 ra = __hmax2(__hadd2(*(__nv_bfloat162*)&pa, *(__nv_bfloat162*)&bA), z);
            __nv_bfloat162 rb = __hmax2(__hadd2(*(__nv_bfloat162*)&pb, *(__nv_bfloat162*)&bB), z);
            hf[tt][j]     = *(uint32_t*)&ra;
            hf[tt][2 + j] = *(uint32_t*)&rb;
        }
    }
}

// Coalesced obs A-fragment loader (float4 + shfl redistribute)
__device__ __forceinline__ void enc_frags(const float* __restrict__ obs,
                                          size_t rbase_row, int t,
                                          int lane, int gr, int c, uint32_t a[4]) {
    const float* p0 = obs + (rbase_row + gr) * NOBS + 16 * t + 4 * c;
    float4 F0 = __ldg((const float4*)p0);
    float4 F1 = __ldg((const float4*)(p0 + 8 * NOBS));
    uint32_t p0xy = packbf(F0.x, F0.y), p0zw = packbf(F0.z, F0.w);
    uint32_t p1xy = packbf(F1.x, F1.y), p1zw = packbf(F1.z, F1.w);
    int srcA = (lane & ~3) | (c >> 1);
    int srcB = srcA + 2;
    uint32_t txy, tzw;
    txy = __shfl_sync(0xffffffffu, p0xy, srcA);
    tzw = __shfl_sync(0xffffffffu, p0zw, srcA);
    a[0] = (c & 1) ? tzw : txy;
    txy = __shfl_sync(0xffffffffu, p1xy, srcA);
    tzw = __shfl_sync(0xffffffffu, p1zw, srcA);
    a[1] = (c & 1) ? tzw : txy;
    txy = __shfl_sync(0xffffffffu, p0xy, srcB);
    tzw = __shfl_sync(0xffffffffu, p0zw, srcB);
    a[2] = (c & 1) ? tzw : txy;
    txy = __shfl_sync(0xffffffffu, p1xy, srcB);
    tzw = __shfl_sync(0xffffffffu, p1zw, srcB);
    a[3] = (c & 1) ? tzw : txy;
}

// In-place dense relu layer over 2 batches x 2 stripes, N split into two halves.
// One LDSM pair feeds 8 MMAs. Half-0 output parks in a 32-reg temp; half-1 pack
// overwrites h (legal: all half-1 MMAs completed), then temp is copied in.
__device__ __forceinline__ void dense64_4(uint32_t (&h)[2][2][4][4],
                                          const __nv_bfloat16* W, const uint32_t* sBH,
                                          int lane, int c) {
    uint32_t th[2][2][2][4];   // half-0 packed output
#pragma unroll
    for (int nh = 0; nh < 2; ++nh) {
        float acc[4][4][4];
#pragma unroll
        for (int s = 0; s < 4; ++s)
#pragma unroll
            for (int nt = 0; nt < 4; ++nt) {
                acc[s][nt][0]=0.f; acc[s][nt][1]=0.f; acc[s][nt][2]=0.f; acc[s][nt][3]=0.f;
            }
#pragma unroll
        for (int t = 0; t < 4; ++t)
            gemm4_ktile<4>(h[0][0][t], h[0][1][t], h[1][0][t], h[1][1][t],
                           W + 16 * t * W_STRIDE + 32 * nh, W_STRIDE,
                           acc[0], acc[1], acc[2], acc[3], lane);
        if (nh == 0) {
            pack_h4(acc[0], th[0][0], sBH, c);
            pack_h4(acc[1], th[0][1], sBH, c);
            pack_h4(acc[2], th[1][0], sBH, c);
            pack_h4(acc[3], th[1][1], sBH, c);
        } else {
            pack_h4(acc[0], &h[0][0][2], sBH + 16, c);
            pack_h4(acc[1], &h[0][1][2], sBH + 16, c);
            pack_h4(acc[2], &h[1][0][2], sBH + 16, c);
            pack_h4(acc[3], &h[1][1][2], sBH + 16, c);
        }
    }
#pragma unroll
    for (int b = 0; b < 2; ++b)
#pragma unroll
        for (int st = 0; st < 2; ++st)
#pragma unroll
            for (int tt = 0; tt < 2; ++tt)
#pragma unroll
                for (int j = 0; j < 4; ++j)
                    h[b][st][tt][j] = th[b][st][tt][j];
}

// Comm round for 2 batches, rank-1 M-packed across batches (rows 0-7 = cs_b0,
// rows 8-15 = cs_b1 -> one R gemm serves both batches). In-place on h.
__device__ __forceinline__ void comm_round2(uint32_t (&h)[2][2][4][4],
                                            const __nv_bfloat16* Wc1, const __nv_bfloat16* Wc2,
                                            const uint32_t* sBH, int lane, int c) {
    // per-batch packed column sums (bf16x2 HADD2 + butterfly)
    uint32_t csPA[2][4], csPB[2][4];
#pragma unroll
    for (int b = 0; b < 2; ++b)
#pragma unroll
        for (int t = 0; t < 4; ++t) {
            uint32_t pA = bf2add(bf2add(h[b][0][t][0], h[b][0][t][1]),
                                 bf2add(h[b][1][t][0], h[b][1][t][1]));
            uint32_t pB = bf2add(bf2add(h[b][0][t][2], h[b][0][t][3]),
                                 bf2add(h[b][1][t][2], h[b][1][t][3]));
#pragma unroll
            for (int m = 4; m < 32; m <<= 1) {
                pA = bf2add(pA, __shfl_xor_sync(0xffffffffu, pA, m));
                pB = bf2add(pB, __shfl_xor_sync(0xffffffffu, pB, m));
            }
            csPA[b][t] = pA;
            csPB[b][t] = pB;
        }

    uint32_t th[2][2][2][4];
#pragma unroll
    for (int nh = 0; nh < 2; ++nh) {
        // R packed: A rows 0-7 = cs_b0, rows 8-15 = cs_b1
        float racc[4][4];
#pragma unroll
        for (int nt = 0; nt < 4; ++nt) {
            racc[nt][0]=0.f; racc[nt][1]=0.f; racc[nt][2]=0.f; racc[nt][3]=0.f;
        }
#pragma unroll
        for (int t = 0; t < 4; ++t) {
            uint32_t a[4];
            a[0] = csPA[0][t]; a[1] = csPA[1][t];
            a[2] = csPB[0][t]; a[3] = csPB[1][t];
            gemm_ktile<4>(a, Wc2 + 16 * t * W_STRIDE + 32 * nh, W_STRIDE, racc, lane);
        }
        // init acc from R: batch b gets racc[nt][2b..2b+1] replicated over rows
        float acc[4][4][4];
#pragma unroll
        for (int nt = 0; nt < 4; ++nt) {
            float l0 = racc[nt][0], h0 = racc[nt][1];
            float l1 = racc[nt][2], h1 = racc[nt][3];
#pragma unroll
            for (int st = 0; st < 2; ++st) {
                acc[st][nt][0] = l0; acc[st][nt][1] = h0;
                acc[st][nt][2] = l0; acc[st][nt][3] = h0;
                acc[2 + st][nt][0] = l1; acc[2 + st][nt][1] = h1;
                acc[2 + st][nt][2] = l1; acc[2 + st][nt][3] = h1;
            }
        }
#pragma unroll
        for (int t = 0; t < 4; ++t)
            gemm4_ktile<4>(h[0][0][t], h[0][1][t], h[1][0][t], h[1][1][t],
                           Wc1 + 16 * t * W_STRIDE + 32 * nh, W_STRIDE,
                           acc[0], acc[1], acc[2], acc[3], lane);
        if (nh == 0) {
            pack_h4(acc[0], th[0][0], sBH, c);
            pack_h4(acc[1], th[0][1], sBH, c);
            pack_h4(acc[2], th[1][0], sBH, c);
            pack_h4(acc[3], th[1][1], sBH, c);
        } else {
            pack_h4(acc[0], &h[0][0][2], sBH + 16, c);
            pack_h4(acc[1], &h[0][1][2], sBH + 16, c);
            pack_h4(acc[2], &h[1][0][2], sBH + 16, c);
            pack_h4(acc[3], &h[1][1][2], sBH + 16, c);
        }
    }
#pragma unroll
    for (int b = 0; b < 2; ++b)
#pragma unroll
        for (int st = 0; st < 2; ++st)
#pragma unroll
            for (int tt = 0; tt < 2; ++tt)
#pragma unroll
                for (int j = 0; j < 4; ++j)
                    h[b][st][tt][j] = th[b][st][tt][j];
}

// ---------------------------------------------------------------------------
// Persistent warp-autonomous CommNet kernel: 12 warps, 2 batches/warp,
// 4-stripe LDSM sharing (1 ldmatrix -> 8 MMAs), N-split, in-place layers.
// ---------------------------------------------------------------------------
__global__ void __launch_bounds__(NTHREADS, 1)
commnet_kernel(const float* __restrict__ obs,
               const float* __restrict__ enc_b,
               const float* __restrict__ comm_b,
               const float* __restrict__ out_b1,
               const float* __restrict__ out_b2,
               const int*   __restrict__ avail,
               float*       __restrict__ out) {
    extern __shared__ __align__(16) char smem_raw[];
    __nv_bfloat16* sWe  = (__nv_bfloat16*)smem_raw;                  // 64  x 72
    __nv_bfloat16* sWc1 = sWe  + NH * W_STRIDE;                      // 128 x 72 (2 rounds)
    __nv_bfloat16* sWc2 = sWc1 + NROUNDS * NH * W_STRIDE;            // 128 x 72 (2 rounds)
    __nv_bfloat16* sWo1 = sWc2 + NROUNDS * NH * W_STRIDE;            // 64  x 72
    __nv_bfloat16* sWo2 = sWo1 + NH * W_STRIDE;                      // 64  x 24
    uint32_t*      sBH  = (uint32_t*)(sWo2 + NH * W2_STRIDE);        // 128 bf16x2 pairs
    float*         sB2  = (float*)(sBH + 128);                       // 16 fp32 (out_b2)

    const int tid  = threadIdx.x;
    const int lane = tid & 31;
    const int c    = lane & 3;
    const int gr   = lane >> 2;

    // ---- prologue: stage weights via cp.async, biases packed to bf16x2 ----
    for (int i = tid; i < 512; i += NTHREADS) {
        int r = i >> 3, ci = i & 7;
        cp16(sWe + r * W_STRIDE + ci * 8, g_enc_w + r * NH + ci * 8);
    }
    for (int i = tid; i < 1024; i += NTHREADS) {
        int r = i >> 3, ci = i & 7;
        cp16(sWc1 + r * W_STRIDE + ci * 8, g_comm_w1 + r * NH + ci * 8);
    }
    for (int i = tid; i < 1024; i += NTHREADS) {
        int r = i >> 3, ci = i & 7;
        cp16(sWc2 + r * W_STRIDE + ci * 8, g_comm_w2 + r * NH + ci * 8);
    }
    for (int i = tid; i < 512; i += NTHREADS) {
        int r = i >> 3, ci = i & 7;
        cp16(sWo1 + r * W_STRIDE + ci * 8, g_out_w1 + r * NH + ci * 8);
    }
    for (int i = tid; i < 128; i += NTHREADS) {
        int r = i >> 1, ci = i & 1;
        cp16(sWo2 + r * W2_STRIDE + ci * 8, g_out_w2 + r * NACT + ci * 8);
    }
    cp_commit();
    // bias pairs: enc [0..32), comm rd0 [32..64), comm rd1 [64..96), out1 [96..128)
    if (tid < 32) sBH[tid]      = packbf(enc_b[2*tid],  enc_b[2*tid+1]);
    if (tid < 64) sBH[32 + tid] = packbf(comm_b[2*tid], comm_b[2*tid+1]);
    if (tid < 32) sBH[96 + tid] = packbf(out_b1[2*tid], out_b1[2*tid+1]);
    if (tid < 16) sB2[tid]      = out_b2[tid];
    cp_wait_all();
    __syncthreads();

    // ---- per-warp unit loop (unit = 2 batches = 64 rows) ----
    unsigned u;
    if (lane == 0) u = atomicAdd(&g_tile_ctr, 1u);
    u = __shfl_sync(0xffffffffu, u, 0);

    uint32_t h[2][2][4][4];              // [batch][stripe][ktile][frag]

    while (u < NUNITS_U) {
        const size_t urow0 = (size_t)u * 64;

        // ---- encoder: h = relu(obs @ enc_w + enc_b), 4-stripe shared LDSM ----
        {
            uint32_t ofrag[2][2][4][4];
#pragma unroll
            for (int b = 0; b < 2; ++b)
#pragma unroll
                for (int st = 0; st < 2; ++st)
#pragma unroll
                    for (int t = 0; t < 4; ++t)
                        enc_frags(obs, urow0 + 32 * b + 16 * st, t, lane, gr, c,
                                  ofrag[b][st][t]);
#pragma unroll
            for (int nh = 0; nh < 2; ++nh) {
                float acc[4][4][4];
#pragma unroll
                for (int s = 0; s < 4; ++s)
#pragma unroll
                    for (int nt = 0; nt < 4; ++nt) {
                        acc[s][nt][0]=0.f; acc[s][nt][1]=0.f; acc[s][nt][2]=0.f; acc[s][nt][3]=0.f;
                    }
#pragma unroll
                for (int t = 0; t < 4; ++t)
                    gemm4_ktile<4>(ofrag[0][0][t], ofrag[0][1][t],
                                   ofrag[1][0][t], ofrag[1][1][t],
                                   sWe + 16 * t * W_STRIDE + 32 * nh, W_STRIDE,
                                   acc[0], acc[1], acc[2], acc[3], lane);
                pack_h4(acc[0], &h[0][0][2 * nh], sBH + 16 * nh, c);
                pack_h4(acc[1], &h[0][1][2 * nh], sBH + 16 * nh, c);
                pack_h4(acc[2], &h[1][0][2 * nh], sBH + 16 * nh, c);
                pack_h4(acc[3], &h[1][1][2 * nh], sBH + 16 * nh, c);
            }
        }

        // ---- grab next unit, prefetch its obs+avail to L2 ----
        unsigned un;
        if (lane == 0) un = atomicAdd(&g_tile_ctr, 1u);
        un = __shfl_sync(0xffffffffu, un, 0);
        if (un < NUNITS_U) {
            const char* ob = (const char*)(obs + (size_t)un * 64 * NOBS);
#pragma unroll
            for (int i = 0; i < 4; ++i) l2pf(ob + lane * 128 + i * 4096);
            l2pf((const char*)(avail + (size_t)un * 64 * NACT) + lane * 128);
        }

        // ---- comm rounds (in-place, rank-1 M-packed across both batches) ----
        comm_round2(h, sWc1,                 sWc2,                 sBH + 32, lane, c);
        comm_round2(h, sWc1 + NH * W_STRIDE, sWc2 + NH * W_STRIDE, sBH + 64, lane, c);

        // ---- out1 (in-place) ----
        dense64_4(h, sWo1, sBH + 96, lane, c);

        // ---- hoist avail loads (overlap L2 latency with out2 MMAs) ----
        int2 av[4][2][2];
        {
            int colb = 2 * c;
#pragma unroll
            for (int s2 = 0; s2 < 4; ++s2)
#pragma unroll
                for (int nt = 0; nt < 2; ++nt)
#pragma unroll
                    for (int half = 0; half < 2; ++half) {
                        size_t grow = urow0 + (size_t)(s2 >> 1) * 32 + (s2 & 1) * 16
                                      + gr + 8 * half;
                        av[s2][nt][half] = __ldg((const int2*)(avail + grow * NACT + nt * 8 + colb));
                    }
        }

        // ---- out2 shared across all 4 stripes (1 ldmatrix -> 8 MMAs) ----
        float acc2[4][2][4];
#pragma unroll
        for (int s2 = 0; s2 < 4; ++s2)
#pragma unroll
            for (int nt = 0; nt < 2; ++nt) {
                acc2[s2][nt][0]=0.f; acc2[s2][nt][1]=0.f; acc2[s2][nt][2]=0.f; acc2[s2][nt][3]=0.f;
            }
#pragma unroll
        for (int t = 0; t < 4; ++t) {
            uint32_t b0, b1, b2, b3;
            ldsm_x4_t(b0, b1, b2, b3,
                      smem_u32(sWo2 + (16 * t + (lane & 15)) * W2_STRIDE + ((lane >> 4) << 3)));
#pragma unroll
            for (int s2 = 0; s2 < 4; ++s2) {
                const uint32_t* A = h[s2 >> 1][s2 & 1][t];
                mma16816(acc2[s2][0], A[0], A[1], A[2], A[3], b0, b1);
                mma16816(acc2[s2][1], A[0], A[1], A[2], A[3], b2, b3);
            }
        }

        // ---- epilogue: bias + mask + store ----
        {
            int colb = 2 * c;
#pragma unroll
            for (int s2 = 0; s2 < 4; ++s2) {
                size_t rowb = urow0 + (size_t)(s2 >> 1) * 32 + (s2 & 1) * 16;
#pragma unroll
                for (int nt = 0; nt < 2; ++nt) {
                    int col  = nt * 8 + colb;
                    float b0 = sB2[col], b1 = sB2[col + 1];
#pragma unroll
                    for (int half = 0; half < 2; ++half) {
                        size_t grow = rowb + gr + 8 * half;
                        int2 a = av[s2][nt][half];
                        float q0 = acc2[s2][nt][half * 2 + 0] + b0;
                        float q1 = acc2[s2][nt][half * 2 + 1] + b1;
                        if (a.x == 0) q0 = -1e10f;
                        if (a.y == 0) q1 = -1e10f;
                        *(float2*)(out + grow * NACT + col) = make_float2(q0, q1);
                    }
                }
            }
        }

        u = un;
    }
}

#define SMEM_BYTES ((64*72 + 2*64*72 + 2*64*72 + 64*72 + 64*24) * 2 + 128 * 4 + 16 * 4 + 64)

// ---------------------------------------------------------------------------
extern "C" void kernel_launch(void* const* d_in, const int* in_sizes, int n_in,
                              void* d_out, int out_size) {
    const float* obs    = (const float*)d_in[0];
    const float* enc_w  = (const float*)d_in[1];
    const float* enc_b  = (const float*)d_in[2];
    const float* comm_w = (const float*)d_in[3];
    const float* comm_b = (const float*)d_in[4];
    const float* out_w1 = (const float*)d_in[5];
    const float* out_b1 = (const float*)d_in[6];
    const float* out_w2 = (const float*)d_in[7];
    const float* out_b2 = (const float*)d_in[8];
    const int*   avail  = (const int*)d_in[9];
    float* out = (float*)d_out;

    cudaFuncSetAttribute(commnet_kernel, cudaFuncAttributeMaxDynamicSharedMemorySize, SMEM_BYTES);

    convert_weights_kernel<<<64, 256>>>(enc_w, comm_w, out_w1, out_w2);
    commnet_kernel<<<NCTAS, NTHREADS, SMEM_BYTES>>>(
        obs, enc_b, comm_b, out_b1, out_b2, avail, out);
}